// round 2
// baseline (speedup 1.0000x reference)
#include <cuda_runtime.h>
#include <cuda_bf16.h>
#include <cstdint>

#define D_MODEL 1024
#define STATE   128
#define BATCH   4
#define SEQ     4096
#define ROWS    (BATCH*SEQ)     /* 16384 */
#define NCHUNK  32
#define DC      32              /* D per scan chunk */
#define RMS_EPS 1.1920929e-07f

// ---------------- scratch (static device arrays; no runtime alloc) ----------------
__device__ float          g_x   [ROWS*D_MODEL];     // gathered embeddings, 67MB
__device__ float          g_bt  [ROWS*STATE];       // sigmoid(x @ W_B^T), 8MB
__device__ float          g_hm  [ROWS*STATE];       // reduced state means, 8MB
__device__ float          g_wbt [D_MODEL*STATE];    // W_B transposed: [k][n]
__device__ float          g_wct [STATE*D_MODEL];    // W_C transposed: [n][d]
__device__ __nv_bfloat16  g_part[NCHUNK*ROWS*STATE];// per-chunk partial sums, 134MB

// ---------------- helpers ----------------
__device__ __forceinline__ unsigned long long pk2(float lo, float hi) {
    unsigned long long r; asm("mov.b64 %0,{%1,%2};" : "=l"(r) : "f"(lo), "f"(hi)); return r;
}
__device__ __forceinline__ void upk2(unsigned long long v, float& lo, float& hi) {
    asm("mov.b64 {%0,%1},%2;" : "=f"(lo), "=f"(hi) : "l"(v));
}
__device__ __forceinline__ unsigned long long fma2(unsigned long long a, unsigned long long b, unsigned long long c) {
    unsigned long long r; asm("fma.rn.f32x2 %0,%1,%2,%3;" : "=l"(r) : "l"(a), "l"(b), "l"(c)); return r;
}
__device__ __forceinline__ unsigned long long mul2(unsigned long long a, unsigned long long b) {
    unsigned long long r; asm("mul.rn.f32x2 %0,%1,%2;" : "=l"(r) : "l"(a), "l"(b)); return r;
}
__device__ __forceinline__ unsigned long long add2(unsigned long long a, unsigned long long b) {
    unsigned long long r; asm("add.rn.f32x2 %0,%1,%2;" : "=l"(r) : "l"(a), "l"(b)); return r;
}
__device__ __forceinline__ float sigmoidf_(float x) { return 1.0f / (1.0f + __expf(-x)); }

__device__ __forceinline__ void cpasync16(void* smem, const void* gmem) {
    unsigned s = (unsigned)__cvta_generic_to_shared(smem);
    asm volatile("cp.async.cg.shared.global [%0],[%1],16;" :: "r"(s), "l"(gmem));
}
#define CP_COMMIT() asm volatile("cp.async.commit_group;")
#define CP_WAIT0()  asm volatile("cp.async.wait_group 0;")

// ---------------- K0: transpose weights ----------------
__global__ void k_prep(const float* __restrict__ WB, const float* __restrict__ WC) {
    int i = blockIdx.x * 256 + threadIdx.x;            // 131072 total
    if (i < D_MODEL * STATE) {
        int k = i >> 7, n = i & 127;                    // g_wbt[k][n] = W_B[n][k]
        g_wbt[i] = WB[n * D_MODEL + k];
        int nn = i >> 10, d = i & 1023;                 // g_wct[n][d] = W_C[d][n]
        g_wct[i] = WC[d * STATE + nn];
    }
}

// ---------------- K1: embedding gather ----------------
__global__ void k_gather(const int* __restrict__ tokens, const float* __restrict__ emb) {
    int row = blockIdx.x;
    int tok = tokens[row];
    const float4* src = (const float4*)(emb + (size_t)tok * D_MODEL);
    float4* dst = (float4*)(g_x + (size_t)row * D_MODEL);
    dst[threadIdx.x] = src[threadIdx.x];                // 256 thr x 16B = 4KB
}

// ---------------- K2: Bt = sigmoid(x @ W_B^T)  [16384x1024]x[1024x128] ----------------
__global__ void __launch_bounds__(256, 1) k_gemm_bt() {
    __shared__ float As[2][128 * 8];   // [row][kk]
    __shared__ float Bs[2][8 * 128];   // [kk][n]
    int t = threadIdx.x;
    int row0 = blockIdx.x * 128;
    int tr = t >> 4, tc = t & 15;

    unsigned long long acc[8][4];
    #pragma unroll
    for (int i = 0; i < 8; i++)
        #pragma unroll
        for (int j = 0; j < 4; j++) acc[i][j] = 0ull;

    // prologue load of k-tile 0
    {
        int r = t >> 1, q = t & 1;
        cpasync16(&As[0][r * 8 + q * 4], &g_x[(size_t)(row0 + r) * D_MODEL + q * 4]);
        int kk = t >> 5, q2 = t & 31;
        cpasync16(&Bs[0][kk * 128 + q2 * 4], &g_wbt[kk * STATE + q2 * 4]);
        CP_COMMIT();
    }

    const int NT = D_MODEL / 8;   // 128 k-tiles
    for (int kt = 0; kt < NT; kt++) {
        CP_WAIT0();
        __syncthreads();
        if (kt + 1 < NT) {
            int k0 = (kt + 1) * 8, buf = (kt + 1) & 1;
            int r = t >> 1, q = t & 1;
            cpasync16(&As[buf][r * 8 + q * 4], &g_x[(size_t)(row0 + r) * D_MODEL + k0 + q * 4]);
            int kk = t >> 5, q2 = t & 31;
            cpasync16(&Bs[buf][kk * 128 + q2 * 4], &g_wbt[(k0 + kk) * STATE + q2 * 4]);
            CP_COMMIT();
        }
        const float* Ab = &As[kt & 1][0];
        const float* Bb = &Bs[kt & 1][0];
        #pragma unroll
        for (int kk = 0; kk < 8; kk++) {
            float4 b0 = *(const float4*)&Bb[kk * 128 + tc * 8];
            float4 b1 = *(const float4*)&Bb[kk * 128 + tc * 8 + 4];
            unsigned long long bp[4] = { pk2(b0.x, b0.y), pk2(b0.z, b0.w),
                                         pk2(b1.x, b1.y), pk2(b1.z, b1.w) };
            #pragma unroll
            for (int i = 0; i < 8; i++) {
                float a = Ab[(tr * 8 + i) * 8 + kk];
                unsigned long long ad = pk2(a, a);
                #pragma unroll
                for (int j = 0; j < 4; j++) acc[i][j] = fma2(ad, bp[j], acc[i][j]);
            }
        }
        __syncthreads();
    }

    // epilogue: sigmoid + store
    #pragma unroll
    for (int i = 0; i < 8; i++) {
        int row = row0 + tr * 8 + i;
        float o[8];
        #pragma unroll
        for (int j = 0; j < 4; j++) upk2(acc[i][j], o[2 * j], o[2 * j + 1]);
        #pragma unroll
        for (int j = 0; j < 8; j++) o[j] = sigmoidf_(o[j]);
        float* dst = &g_bt[(size_t)row * STATE + tc * 8];
        *(float4*)(dst)     = make_float4(o[0], o[1], o[2], o[3]);
        *(float4*)(dst + 4) = make_float4(o[4], o[5], o[6], o[7]);
    }
}

// ---------------- K3: the scan ----------------
// grid = 128 CTAs: (b, chunk). 128 threads: thread = one n, owns DC=32 d's in regs.
__global__ void __launch_bounds__(128, 1) k_scan(const float* __restrict__ A_log) {
    __shared__ float xs[2][16][32];
    __shared__ float bs[2][16][128];
    __shared__ __nv_bfloat16 outs[16 * 128];

    int tid = threadIdx.x;                 // n
    int c = blockIdx.x & 31;               // chunk
    int b = blockIdx.x >> 5;               // batch
    int d0 = c * DC;
    int rbase = b * SEQ;

    // decay factors (pairs over d)
    unsigned long long a2[16], h2[16];
    #pragma unroll
    for (int j = 0; j < 16; j++) {
        float alo = sigmoidf_(A_log[(d0 + 2 * j)     * STATE + tid]);
        float ahi = sigmoidf_(A_log[(d0 + 2 * j + 1) * STATE + tid]);
        a2[j] = pk2(alo, ahi);
        h2[j] = 0ull;
    }

    // prologue: tile 0
    {
        int ss = tid >> 3, q = tid & 7;
        cpasync16(&xs[0][ss][q * 4], &g_x[(size_t)(rbase + ss) * D_MODEL + d0 + q * 4]);
        #pragma unroll
        for (int jj = 0; jj < 4; jj++) {
            int idx = tid + 128 * jj, s2 = idx >> 5, q2 = idx & 31;
            cpasync16(&bs[0][s2][q2 * 4], &g_bt[(size_t)(rbase + s2) * STATE + q2 * 4]);
        }
        CP_COMMIT();
    }

    const int NT = SEQ / 16;   // 256 tiles
    for (int tt = 0; tt < NT; tt++) {
        CP_WAIT0();
        __syncthreads();
        if (tt + 1 < NT) {
            int s0n = (tt + 1) * 16, buf = (tt + 1) & 1;
            int ss = tid >> 3, q = tid & 7;
            cpasync16(&xs[buf][ss][q * 4], &g_x[(size_t)(rbase + s0n + ss) * D_MODEL + d0 + q * 4]);
            #pragma unroll
            for (int jj = 0; jj < 4; jj++) {
                int idx = tid + 128 * jj, s2 = idx >> 5, q2 = idx & 31;
                cpasync16(&bs[buf][s2][q2 * 4], &g_bt[(size_t)(rbase + s0n + s2) * STATE + q2 * 4]);
            }
            CP_COMMIT();
        }
        int cur = tt & 1;
        #pragma unroll
        for (int ss = 0; ss < 16; ss++) {
            float btv = bs[cur][ss][tid];
            unsigned long long bt2 = pk2(btv, btv);
            unsigned long long acc[4] = {0ull, 0ull, 0ull, 0ull};
            #pragma unroll
            for (int j = 0; j < 16; j++) {
                float2 xv = *(const float2*)&xs[cur][ss][2 * j];
                unsigned long long x2 = pk2(xv.x, xv.y);
                unsigned long long t2 = mul2(bt2, x2);
                h2[j] = fma2(a2[j], h2[j], t2);
                acc[j & 3] = add2(acc[j & 3], h2[j]);
            }
            unsigned long long s01 = add2(acc[0], acc[1]);
            unsigned long long s23 = add2(acc[2], acc[3]);
            unsigned long long st  = add2(s01, s23);
            float lo, hi; upk2(st, lo, hi);
            float partial = (lo + hi) * (1.0f / 1024.0f);
            outs[ss * 128 + tid] = __float2bfloat16_rn(partial);
        }
        __syncthreads();
        // flush 16 steps of partials: 4KB contiguous
        {
            int s0 = tt * 16;
            const uint4* so = (const uint4*)outs;
            uint4* gp = (uint4*)g_part;
            size_t base = (size_t)(c * ROWS + rbase + s0) * 16;  // uint4 units (128 bf16 / row / 8)
            gp[base + tid]       = so[tid];
            gp[base + 128 + tid] = so[128 + tid];
        }
    }
}

// ---------------- K4: reduce partials -> hm ----------------
__global__ void k_reduce() {
    int g = blockIdx.x * 256 + threadIdx.x;   // 8192 blocks => 2.1M threads
    int row = g >> 7, n = g & 127;
    float s = 0.0f;
    #pragma unroll
    for (int c = 0; c < NCHUNK; c++)
        s += __bfloat162float(g_part[((size_t)c * ROWS + row) * STATE + n]);
    g_hm[(size_t)row * STATE + n] = s;
}

// ---------------- K5: y = hm @ W_C^T + D*x  (pre-norm), [16384x128]x[128x1024] ----------------
__global__ void __launch_bounds__(256, 1) k_gemm_y(float* __restrict__ out,
                                                   const float* __restrict__ Dp) {
    __shared__ float As[2][128 * 8];   // hm rows [row][kk]
    __shared__ float Bs[2][8 * 128];   // wct [kk][d]
    int t = threadIdx.x;
    int mt = blockIdx.x >> 3;
    int nt = blockIdx.x & 7;
    int row0 = mt * 128;
    int d0 = nt * 128;
    int tr = t >> 4, tc = t & 15;

    unsigned long long acc[8][4];
    #pragma unroll
    for (int i = 0; i < 8; i++)
        #pragma unroll
        for (int j = 0; j < 4; j++) acc[i][j] = 0ull;

    {
        int r = t >> 1, q = t & 1;
        cpasync16(&As[0][r * 8 + q * 4], &g_hm[(size_t)(row0 + r) * STATE + q * 4]);
        int kk = t >> 5, q2 = t & 31;
        cpasync16(&Bs[0][kk * 128 + q2 * 4], &g_wct[(size_t)kk * D_MODEL + d0 + q2 * 4]);
        CP_COMMIT();
    }

    const int NT = STATE / 8;  // 16 k-tiles
    for (int kt = 0; kt < NT; kt++) {
        CP_WAIT0();
        __syncthreads();
        if (kt + 1 < NT) {
            int k0 = (kt + 1) * 8, buf = (kt + 1) & 1;
            int r = t >> 1, q = t & 1;
            cpasync16(&As[buf][r * 8 + q * 4], &g_hm[(size_t)(row0 + r) * STATE + k0 + q * 4]);
            int kk = t >> 5, q2 = t & 31;
            cpasync16(&Bs[buf][kk * 128 + q2 * 4], &g_wct[(size_t)(k0 + kk) * D_MODEL + d0 + q2 * 4]);
            CP_COMMIT();
        }
        const float* Ab = &As[kt & 1][0];
        const float* Bb = &Bs[kt & 1][0];
        #pragma unroll
        for (int kk = 0; kk < 8; kk++) {
            float4 b0 = *(const float4*)&Bb[kk * 128 + tc * 8];
            float4 b1 = *(const float4*)&Bb[kk * 128 + tc * 8 + 4];
            unsigned long long bp[4] = { pk2(b0.x, b0.y), pk2(b0.z, b0.w),
                                         pk2(b1.x, b1.y), pk2(b1.z, b1.w) };
            #pragma unroll
            for (int i = 0; i < 8; i++) {
                float a = Ab[(tr * 8 + i) * 8 + kk];
                unsigned long long ad = pk2(a, a);
                #pragma unroll
                for (int j = 0; j < 4; j++) acc[i][j] = fma2(ad, bp[j], acc[i][j]);
            }
        }
        __syncthreads();
    }

    // epilogue: + D_param*x, store pre-norm y
    float4 dpa = *(const float4*)&Dp[d0 + tc * 8];
    float4 dpb = *(const float4*)&Dp[d0 + tc * 8 + 4];
    #pragma unroll
    for (int i = 0; i < 8; i++) {
        int row = row0 + tr * 8 + i;
        const float* xr = &g_x[(size_t)row * D_MODEL + d0 + tc * 8];
        float4 xa = *(const float4*)xr;
        float4 xb = *(const float4*)(xr + 4);
        float o[8];
        #pragma unroll
        for (int j = 0; j < 4; j++) upk2(acc[i][j], o[2 * j], o[2 * j + 1]);
        o[0] += dpa.x * xa.x; o[1] += dpa.y * xa.y; o[2] += dpa.z * xa.z; o[3] += dpa.w * xa.w;
        o[4] += dpb.x * xb.x; o[5] += dpb.y * xb.y; o[6] += dpb.z * xb.z; o[7] += dpb.w * xb.w;
        float* dst = out + (size_t)row * D_MODEL + d0 + tc * 8;
        *(float4*)(dst)     = make_float4(o[0], o[1], o[2], o[3]);
        *(float4*)(dst + 4) = make_float4(o[4], o[5], o[6], o[7]);
    }
}

// ---------------- K6: RMSNorm in place ----------------
__global__ void k_rms(float* __restrict__ out, const float* __restrict__ w) {
    int row = blockIdx.x;
    int t = threadIdx.x;
    float4* p = (float4*)(out + (size_t)row * D_MODEL);
    float4 v = p[t];
    float ss = v.x * v.x + v.y * v.y + v.z * v.z + v.w * v.w;
    #pragma unroll
    for (int off = 16; off > 0; off >>= 1) ss += __shfl_xor_sync(0xffffffffu, ss, off);
    __shared__ float red[8];
    if ((t & 31) == 0) red[t >> 5] = ss;
    __syncthreads();
    if (t < 32) {
        float v2 = (t < 8) ? red[t] : 0.0f;
        #pragma unroll
        for (int off = 4; off > 0; off >>= 1) v2 += __shfl_xor_sync(0xffffffffu, v2, off);
        if (t == 0) red[0] = v2;
    }
    __syncthreads();
    float sc = rsqrtf(red[0] * (1.0f / 1024.0f) + RMS_EPS);
    const float4* w4 = (const float4*)w;
    float4 wv = w4[t];
    v.x *= sc * wv.x; v.y *= sc * wv.y; v.z *= sc * wv.z; v.w *= sc * wv.w;
    p[t] = v;
}

// ---------------- launch ----------------
extern "C" void kernel_launch(void* const* d_in, const int* in_sizes, int n_in,
                              void* d_out, int out_size) {
    (void)in_sizes; (void)n_in; (void)out_size;
    const int*   tokens = (const int*)  d_in[0];
    const float* emb    = (const float*)d_in[1];
    const float* A_log  = (const float*)d_in[2];
    const float* W_B    = (const float*)d_in[3];
    const float* W_C    = (const float*)d_in[4];
    const float* Dp     = (const float*)d_in[5];
    const float* nw     = (const float*)d_in[6];
    float* out = (float*)d_out;

    k_prep<<<512, 256>>>(W_B, W_C);
    k_gather<<<ROWS, 256>>>(tokens, emb);
    k_gemm_bt<<<ROWS / 128, 256>>>();
    k_scan<<<BATCH * NCHUNK, 128>>>(A_log);
    k_reduce<<<ROWS * STATE / 256, 256>>>();
    k_gemm_y<<<(ROWS / 128) * (D_MODEL / 128), 256>>>(out, Dp);
    k_rms<<<ROWS, 256>>>(out, nw);
}

// round 5
// speedup vs baseline: 1.0048x; 1.0048x over previous
#include <cuda_runtime.h>
#include <cuda_bf16.h>
#include <cstdint>

#define D_MODEL 1024
#define STATE   128
#define BATCH   4
#define SEQ     4096
#define ROWS    (BATCH*SEQ)     /* 16384 */
#define NCHUNK  32
#define DC      32              /* D per scan chunk */
#define RMS_EPS 1.1920929e-07f

// ---------------- scratch (static device arrays; no runtime alloc) ----------------
__device__ float          g_x   [ROWS*D_MODEL];     // gathered embeddings, 67MB
__device__ float          g_bt  [ROWS*STATE];       // sigmoid(x @ W_B^T), 8MB
__device__ float          g_hm  [ROWS*STATE];       // reduced state means, 8MB
__device__ float          g_wbt [D_MODEL*STATE];    // W_B transposed: [k][n]
__device__ float          g_wct [STATE*D_MODEL];    // W_C transposed: [n][d]
__device__ __nv_bfloat16  g_part[NCHUNK*ROWS*STATE];// per-chunk partial sums, 134MB

// ---------------- helpers ----------------
__device__ __forceinline__ unsigned long long pk2(float lo, float hi) {
    unsigned long long r; asm("mov.b64 %0,{%1,%2};" : "=l"(r) : "f"(lo), "f"(hi)); return r;
}
__device__ __forceinline__ void upk2(unsigned long long v, float& lo, float& hi) {
    asm("mov.b64 {%0,%1},%2;" : "=f"(lo), "=f"(hi) : "l"(v));
}
__device__ __forceinline__ unsigned long long fma2(unsigned long long a, unsigned long long b, unsigned long long c) {
    unsigned long long r; asm("fma.rn.f32x2 %0,%1,%2,%3;" : "=l"(r) : "l"(a), "l"(b), "l"(c)); return r;
}
__device__ __forceinline__ unsigned long long mul2(unsigned long long a, unsigned long long b) {
    unsigned long long r; asm("mul.rn.f32x2 %0,%1,%2;" : "=l"(r) : "l"(a), "l"(b)); return r;
}
__device__ __forceinline__ unsigned long long add2(unsigned long long a, unsigned long long b) {
    unsigned long long r; asm("add.rn.f32x2 %0,%1,%2;" : "=l"(r) : "l"(a), "l"(b)); return r;
}
__device__ __forceinline__ float sigmoidf_(float x) { return 1.0f / (1.0f + __expf(-x)); }

__device__ __forceinline__ void cpasync16(void* smem, const void* gmem) {
    unsigned s = (unsigned)__cvta_generic_to_shared(smem);
    asm volatile("cp.async.cg.shared.global [%0],[%1],16;" :: "r"(s), "l"(gmem));
}
#define CP_COMMIT() asm volatile("cp.async.commit_group;")
#define CP_WAIT0()  asm volatile("cp.async.wait_group 0;")

// ---------------- K0: transpose weights ----------------
__global__ void k_prep(const float* __restrict__ WB, const float* __restrict__ WC) {
    int i = blockIdx.x * 256 + threadIdx.x;            // 131072 total
    if (i < D_MODEL * STATE) {
        int k = i >> 7, n = i & 127;                    // g_wbt[k][n] = W_B[n][k]
        g_wbt[i] = WB[n * D_MODEL + k];
        int nn = i >> 10, d = i & 1023;                 // g_wct[n][d] = W_C[d][n]
        g_wct[i] = WC[d * STATE + nn];
    }
}

// ---------------- K1: embedding gather ----------------
__global__ void k_gather(const int* __restrict__ tokens, const float* __restrict__ emb) {
    int row = blockIdx.x;
    int tok = tokens[row];
    const float4* src = (const float4*)(emb + (size_t)tok * D_MODEL);
    float4* dst = (float4*)(g_x + (size_t)row * D_MODEL);
    dst[threadIdx.x] = src[threadIdx.x];                // 256 thr x 16B = 4KB
}

// ---------------- K2: Bt = sigmoid(x @ W_B^T)  [16384x1024]x[1024x128] ----------------
__global__ void __launch_bounds__(256, 1) k_gemm_bt() {
    __shared__ float As[2][128 * 8];   // [row][kk]
    __shared__ float Bs[2][8 * 128];   // [kk][n]
    int t = threadIdx.x;
    int row0 = blockIdx.x * 128;
    int tr = t >> 4, tc = t & 15;

    unsigned long long acc[8][4];
    #pragma unroll
    for (int i = 0; i < 8; i++)
        #pragma unroll
        for (int j = 0; j < 4; j++) acc[i][j] = 0ull;

    // prologue load of k-tile 0
    {
        int r = t >> 1, q = t & 1;
        cpasync16(&As[0][r * 8 + q * 4], &g_x[(size_t)(row0 + r) * D_MODEL + q * 4]);
        int kk = t >> 5, q2 = t & 31;
        cpasync16(&Bs[0][kk * 128 + q2 * 4], &g_wbt[kk * STATE + q2 * 4]);
        CP_COMMIT();
    }

    const int NT = D_MODEL / 8;   // 128 k-tiles
    for (int kt = 0; kt < NT; kt++) {
        CP_WAIT0();
        __syncthreads();
        if (kt + 1 < NT) {
            int k0 = (kt + 1) * 8, buf = (kt + 1) & 1;
            int r = t >> 1, q = t & 1;
            cpasync16(&As[buf][r * 8 + q * 4], &g_x[(size_t)(row0 + r) * D_MODEL + k0 + q * 4]);
            int kk = t >> 5, q2 = t & 31;
            cpasync16(&Bs[buf][kk * 128 + q2 * 4], &g_wbt[(k0 + kk) * STATE + q2 * 4]);
            CP_COMMIT();
        }
        const float* Ab = &As[kt & 1][0];
        const float* Bb = &Bs[kt & 1][0];
        #pragma unroll
        for (int kk = 0; kk < 8; kk++) {
            float4 b0 = *(const float4*)&Bb[kk * 128 + tc * 8];
            float4 b1 = *(const float4*)&Bb[kk * 128 + tc * 8 + 4];
            unsigned long long bp[4] = { pk2(b0.x, b0.y), pk2(b0.z, b0.w),
                                         pk2(b1.x, b1.y), pk2(b1.z, b1.w) };
            #pragma unroll
            for (int i = 0; i < 8; i++) {
                float a = Ab[(tr * 8 + i) * 8 + kk];
                unsigned long long ad = pk2(a, a);
                #pragma unroll
                for (int j = 0; j < 4; j++) acc[i][j] = fma2(ad, bp[j], acc[i][j]);
            }
        }
        __syncthreads();
    }

    // epilogue: sigmoid + store
    #pragma unroll
    for (int i = 0; i < 8; i++) {
        int row = row0 + tr * 8 + i;
        float o[8];
        #pragma unroll
        for (int j = 0; j < 4; j++) upk2(acc[i][j], o[2 * j], o[2 * j + 1]);
        #pragma unroll
        for (int j = 0; j < 8; j++) o[j] = sigmoidf_(o[j]);
        float* dst = &g_bt[(size_t)row * STATE + tc * 8];
        *(float4*)(dst)     = make_float4(o[0], o[1], o[2], o[3]);
        *(float4*)(dst + 4) = make_float4(o[4], o[5], o[6], o[7]);
    }
}

// ---------------- K3: the scan ----------------
// grid = 128 CTAs: (b, chunk). 256 threads: (half, n). Each half owns 16 d's
// (8 f32x2 state pairs) in registers -> 2 warps/SMSP for fma-pipe saturation.
__global__ void __launch_bounds__(256, 1) k_scan(const float* __restrict__ A_log) {
    __shared__ float xs[2][16][32];       // 4KB
    __shared__ float bs[2][16][128];      // 16KB
    __shared__ float outs[2][16][128];    // 16KB (per-half fp32 partial sums)

    int tid  = threadIdx.x;
    int half = tid >> 7;                   // 0/1: which 16-d sub-chunk
    int nid  = tid & 127;                  // state index n
    int c = blockIdx.x & 31;               // chunk
    int b = blockIdx.x >> 5;               // batch
    int d0 = c * DC;
    int dbase = d0 + half * 16;
    int rbase = b * SEQ;

    // decay factors (8 pairs over d)
    unsigned long long a2[8], h2[8];
    #pragma unroll
    for (int j = 0; j < 8; j++) {
        float alo = sigmoidf_(A_log[(dbase + 2 * j)     * STATE + nid]);
        float ahi = sigmoidf_(A_log[(dbase + 2 * j + 1) * STATE + nid]);
        a2[j] = pk2(alo, ahi);
        h2[j] = 0ull;
    }

    // prologue: tile 0
    {
        if (tid < 128) {
            int ss = tid >> 3, q = tid & 7;
            cpasync16(&xs[0][ss][q * 4], &g_x[(size_t)(rbase + ss) * D_MODEL + d0 + q * 4]);
        }
        #pragma unroll
        for (int jj = 0; jj < 2; jj++) {
            int idx = tid + 256 * jj, s2 = idx >> 5, q2 = idx & 31;
            cpasync16(&bs[0][s2][q2 * 4], &g_bt[(size_t)(rbase + s2) * STATE + q2 * 4]);
        }
        CP_COMMIT();
    }

    const int NT = SEQ / 16;   // 256 tiles
    for (int tt = 0; tt < NT; tt++) {
        CP_WAIT0();
        __syncthreads();   // also protects outs reuse (flush of prev tile done)
        if (tt + 1 < NT) {
            int s0n = (tt + 1) * 16, buf = (tt + 1) & 1;
            if (tid < 128) {
                int ss = tid >> 3, q = tid & 7;
                cpasync16(&xs[buf][ss][q * 4], &g_x[(size_t)(rbase + s0n + ss) * D_MODEL + d0 + q * 4]);
            }
            #pragma unroll
            for (int jj = 0; jj < 2; jj++) {
                int idx = tid + 256 * jj, s2 = idx >> 5, q2 = idx & 31;
                cpasync16(&bs[buf][s2][q2 * 4], &g_bt[(size_t)(rbase + s0n + s2) * STATE + q2 * 4]);
            }
            CP_COMMIT();
        }
        int cur = tt & 1;
        #pragma unroll
        for (int ss = 0; ss < 16; ss++) {
            float btv = bs[cur][ss][nid];
            unsigned long long bt2 = pk2(btv, btv);
            unsigned long long acc[4] = {0ull, 0ull, 0ull, 0ull};
            #pragma unroll
            for (int j = 0; j < 8; j++) {
                float2 xv = *(const float2*)&xs[cur][ss][half * 16 + 2 * j];
                unsigned long long x2 = pk2(xv.x, xv.y);
                unsigned long long t2 = mul2(bt2, x2);
                h2[j] = fma2(a2[j], h2[j], t2);
                acc[j & 3] = add2(acc[j & 3], h2[j]);
            }
            unsigned long long s01 = add2(acc[0], acc[1]);
            unsigned long long s23 = add2(acc[2], acc[3]);
            unsigned long long st  = add2(s01, s23);
            float lo, hi; upk2(st, lo, hi);
            outs[half][ss][nid] = lo + hi;
        }
        __syncthreads();
        // flush 16 steps: combine halves, scale, bf16-convert, 4KB store
        {
            int s = tid >> 4, g = tid & 15;
            const float4* o0 = (const float4*)&outs[0][s][g * 8];
            const float4* o1 = (const float4*)&outs[1][s][g * 8];
            float4 x0 = o0[0], x1 = o0[1];
            float4 y0 = o1[0], y1 = o1[1];
            const float sc = 1.0f / 1024.0f;
            float v[8];
            v[0] = (x0.x + y0.x) * sc; v[1] = (x0.y + y0.y) * sc;
            v[2] = (x0.z + y0.z) * sc; v[3] = (x0.w + y0.w) * sc;
            v[4] = (x1.x + y1.x) * sc; v[5] = (x1.y + y1.y) * sc;
            v[6] = (x1.z + y1.z) * sc; v[7] = (x1.w + y1.w) * sc;
            __nv_bfloat162 p0 = __floats2bfloat162_rn(v[0], v[1]);
            __nv_bfloat162 p1 = __floats2bfloat162_rn(v[2], v[3]);
            __nv_bfloat162 p2 = __floats2bfloat162_rn(v[4], v[5]);
            __nv_bfloat162 p3 = __floats2bfloat162_rn(v[6], v[7]);
            uint4 pk;
            pk.x = *(unsigned*)&p0; pk.y = *(unsigned*)&p1;
            pk.z = *(unsigned*)&p2; pk.w = *(unsigned*)&p3;
            size_t row = (size_t)c * ROWS + rbase + tt * 16 + s;
            ((uint4*)g_part)[row * 16 + g] = pk;
        }
    }
}

// ---------------- K4: reduce partials -> hm ----------------
__global__ void k_reduce() {
    int g = blockIdx.x * 256 + threadIdx.x;   // 8192 blocks => 2.1M threads
    int row = g >> 7, n = g & 127;
    float s = 0.0f;
    #pragma unroll
    for (int c = 0; c < NCHUNK; c++)
        s += __bfloat162float(g_part[((size_t)c * ROWS + row) * STATE + n]);
    g_hm[(size_t)row * STATE + n] = s;
}

// ---------------- K5: y = hm @ W_C^T + D*x  (pre-norm), [16384x128]x[128x1024] ----------------
__global__ void __launch_bounds__(256, 1) k_gemm_y(float* __restrict__ out,
                                                   const float* __restrict__ Dp) {
    __shared__ float As[2][128 * 8];   // hm rows [row][kk]
    __shared__ float Bs[2][8 * 128];   // wct [kk][d]
    int t = threadIdx.x;
    int mt = blockIdx.x >> 3;
    int nt = blockIdx.x & 7;
    int row0 = mt * 128;
    int d0 = nt * 128;
    int tr = t >> 4, tc = t & 15;

    unsigned long long acc[8][4];
    #pragma unroll
    for (int i = 0; i < 8; i++)
        #pragma unroll
        for (int j = 0; j < 4; j++) acc[i][j] = 0ull;

    {
        int r = t >> 1, q = t & 1;
        cpasync16(&As[0][r * 8 + q * 4], &g_hm[(size_t)(row0 + r) * STATE + q * 4]);
        int kk = t >> 5, q2 = t & 31;
        cpasync16(&Bs[0][kk * 128 + q2 * 4], &g_wct[(size_t)kk * D_MODEL + d0 + q2 * 4]);
        CP_COMMIT();
    }

    const int NT = STATE / 8;  // 16 k-tiles
    for (int kt = 0; kt < NT; kt++) {
        CP_WAIT0();
        __syncthreads();
        if (kt + 1 < NT) {
            int k0 = (kt + 1) * 8, buf = (kt + 1) & 1;
            int r = t >> 1, q = t & 1;
            cpasync16(&As[buf][r * 8 + q * 4], &g_hm[(size_t)(row0 + r) * STATE + k0 + q * 4]);
            int kk = t >> 5, q2 = t & 31;
            cpasync16(&Bs[buf][kk * 128 + q2 * 4], &g_wct[(size_t)(k0 + kk) * D_MODEL + d0 + q2 * 4]);
            CP_COMMIT();
        }
        const float* Ab = &As[kt & 1][0];
        const float* Bb = &Bs[kt & 1][0];
        #pragma unroll
        for (int kk = 0; kk < 8; kk++) {
            float4 b0 = *(const float4*)&Bb[kk * 128 + tc * 8];
            float4 b1 = *(const float4*)&Bb[kk * 128 + tc * 8 + 4];
            unsigned long long bp[4] = { pk2(b0.x, b0.y), pk2(b0.z, b0.w),
                                         pk2(b1.x, b1.y), pk2(b1.z, b1.w) };
            #pragma unroll
            for (int i = 0; i < 8; i++) {
                float a = Ab[(tr * 8 + i) * 8 + kk];
                unsigned long long ad = pk2(a, a);
                #pragma unroll
                for (int j = 0; j < 4; j++) acc[i][j] = fma2(ad, bp[j], acc[i][j]);
            }
        }
        __syncthreads();
    }

    // epilogue: + D_param*x, store pre-norm y
    float4 dpa = *(const float4*)&Dp[d0 + tc * 8];
    float4 dpb = *(const float4*)&Dp[d0 + tc * 8 + 4];
    #pragma unroll
    for (int i = 0; i < 8; i++) {
        int row = row0 + tr * 8 + i;
        const float* xr = &g_x[(size_t)row * D_MODEL + d0 + tc * 8];
        float4 xa = *(const float4*)xr;
        float4 xb = *(const float4*)(xr + 4);
        float o[8];
        #pragma unroll
        for (int j = 0; j < 4; j++) upk2(acc[i][j], o[2 * j], o[2 * j + 1]);
        o[0] += dpa.x * xa.x; o[1] += dpa.y * xa.y; o[2] += dpa.z * xa.z; o[3] += dpa.w * xa.w;
        o[4] += dpb.x * xb.x; o[5] += dpb.y * xb.y; o[6] += dpb.z * xb.z; o[7] += dpb.w * xb.w;
        float* dst = out + (size_t)row * D_MODEL + d0 + tc * 8;
        *(float4*)(dst)     = make_float4(o[0], o[1], o[2], o[3]);
        *(float4*)(dst + 4) = make_float4(o[4], o[5], o[6], o[7]);
    }
}

// ---------------- K6: RMSNorm in place ----------------
__global__ void k_rms(float* __restrict__ out, const float* __restrict__ w) {
    int row = blockIdx.x;
    int t = threadIdx.x;
    float4* p = (float4*)(out + (size_t)row * D_MODEL);
    float4 v = p[t];
    float ss = v.x * v.x + v.y * v.y + v.z * v.z + v.w * v.w;
    #pragma unroll
    for (int off = 16; off > 0; off >>= 1) ss += __shfl_xor_sync(0xffffffffu, ss, off);
    __shared__ float red[8];
    if ((t & 31) == 0) red[t >> 5] = ss;
    __syncthreads();
    if (t < 32) {
        float v2 = (t < 8) ? red[t] : 0.0f;
        #pragma unroll
        for (int off = 4; off > 0; off >>= 1) v2 += __shfl_xor_sync(0xffffffffu, v2, off);
        if (t == 0) red[0] = v2;
    }
    __syncthreads();
    float sc = rsqrtf(red[0] * (1.0f / 1024.0f) + RMS_EPS);
    const float4* w4 = (const float4*)w;
    float4 wv = w4[t];
    v.x *= sc * wv.x; v.y *= sc * wv.y; v.z *= sc * wv.z; v.w *= sc * wv.w;
    p[t] = v;
}

// ---------------- launch ----------------
extern "C" void kernel_launch(void* const* d_in, const int* in_sizes, int n_in,
                              void* d_out, int out_size) {
    (void)in_sizes; (void)n_in; (void)out_size;
    const int*   tokens = (const int*)  d_in[0];
    const float* emb    = (const float*)d_in[1];
    const float* A_log  = (const float*)d_in[2];
    const float* W_B    = (const float*)d_in[3];
    const float* W_C    = (const float*)d_in[4];
    const float* Dp     = (const float*)d_in[5];
    const float* nw     = (const float*)d_in[6];
    float* out = (float*)d_out;

    k_prep<<<512, 256>>>(W_B, W_C);
    k_gather<<<ROWS, 256>>>(tokens, emb);
    k_gemm_bt<<<ROWS / 128, 256>>>();
    k_scan<<<BATCH * NCHUNK, 256>>>(A_log);
    k_reduce<<<ROWS * STATE / 256, 256>>>();
    k_gemm_y<<<(ROWS / 128) * (D_MODEL / 128), 256>>>(out, Dp);
    k_rms<<<ROWS, 256>>>(out, nw);
}